// round 2
// baseline (speedup 1.0000x reference)
#include <cuda_runtime.h>
#include <cuda.h>
#include <cstdint>

// ===================== constants =====================
#define NNODES   16384
#define HDIM     128
#define TILE_M   128
#define TILE_N   128
#define KT       32             // fp32 elems per K-stage = 128 bytes = 1 SW128 row
#define STAGES   5
#define KITERS   (NNODES / KT)  // 512

#define A_STAGE_BYTES (TILE_M * KT * 4)   // 16384
#define B_STAGE_BYTES (TILE_N * KT * 4)   // 16384
#define STAGE_TX      (A_STAGE_BYTES + B_STAGE_BYTES)

// smem layout (dynamic)
#define SM_FULL    0      // STAGES mbarriers (8B each)
#define SM_DONE    64     // STAGES mbarriers
#define SM_A       1024
#define SM_B       (SM_A + STAGES * A_STAGE_BYTES)
#define SMEM_TOTAL (SM_B + STAGES * B_STAGE_BYTES)   // 164864

#define BIG_THREADS 160   // warps 0-3 compute (2x2 of 64x64), warp 4 TMA producer

// scratch (allocation-free rule: __device__ globals)
__device__ __align__(1024) float g_bufA[128UL * 16384];   // t1^T / t2^T  [H][N]
__device__ __align__(1024) float g_bufH[16384UL * 128];   // h1 / h2      [N][H]

// ===================== PTX helpers =====================
__device__ __forceinline__ uint32_t smem_u32(const void* p) {
    uint32_t a;
    asm("{ .reg .u64 t; cvta.to.shared.u64 t, %1; cvt.u32.u64 %0, t; }" : "=r"(a) : "l"(p));
    return a;
}

#define MBAR_INIT(addr, cnt) \
    asm volatile("mbarrier.init.shared.b64 [%0], %1;" :: "r"(addr), "r"(cnt) : "memory")
#define MBAR_EXPECT_TX(addr, bytes) \
    asm volatile("mbarrier.arrive.expect_tx.shared.b64 _, [%0], %1;" :: "r"(addr), "r"(bytes) : "memory")
#define MBAR_ARRIVE(addr) \
    asm volatile("mbarrier.arrive.shared.b64 _, [%0];" :: "r"(addr) : "memory")

#define MBAR_WAIT(addr, parity) do {                                            \
    uint32_t _m = (addr), _p = (parity), _d;                                    \
    asm volatile("{\n\t.reg .pred p;\n\t"                                       \
        "mbarrier.try_wait.parity.acquire.cta.shared::cta.b64 p, [%1], %2;\n\t" \
        "selp.b32 %0, 1, 0, p;\n\t}" : "=r"(_d) : "r"(_m), "r"(_p) : "memory"); \
    if (!_d) {                                                                  \
        asm volatile("{\n\t.reg .pred P1;\n\t"                                  \
        "WL%=:\n\t"                                                             \
        "mbarrier.try_wait.parity.acquire.cta.shared::cta.b64 P1, [%0], %1, 0x989680;\n\t" \
        "@P1 bra.uni WD%=;\n\t"                                                 \
        "bra.uni WL%=;\n\t"                                                     \
        "WD%=:\n\t}" :: "r"(_m), "r"(_p) : "memory");                           \
    } } while (0)

__device__ __forceinline__ void tma_2d(uint32_t smem_dst, const CUtensorMap* map,
                                       int32_t cx, int32_t cy, uint32_t mbar) {
    asm volatile(
        "cp.async.bulk.tensor.2d.shared::cta.global.tile.mbarrier::complete_tx::bytes "
        "[%0], [%1, {%2, %3}], [%4];"
        :: "r"(smem_dst), "l"(map), "r"(cx), "r"(cy), "r"(mbar) : "memory");
}

__device__ __forceinline__ uint32_t f2tf32(float v) {
    uint32_t r;
    asm("cvt.rna.tf32.f32 %0, %1;" : "=r"(r) : "f"(v));
    return r;
}

__device__ __forceinline__ void mma_tf32(float* c, const uint32_t* a, const uint32_t* b) {
    asm volatile("mma.sync.aligned.m16n8k8.row.col.f32.tf32.tf32.f32 "
        "{%0,%1,%2,%3}, {%4,%5,%6,%7}, {%8,%9}, {%0,%1,%2,%3};"
        : "+f"(c[0]), "+f"(c[1]), "+f"(c[2]), "+f"(c[3])
        : "r"(a[0]), "r"(a[1]), "r"(a[2]), "r"(a[3]), "r"(b[0]), "r"(b[1]));
}

// ===================== big GEMM: out[m][n] = relu(bias[n] + sum_k A[m][k]*Bt[n][k]) =====================
// A via TMA SW128 [128m x 32k] per stage; Bt via TMA SW128 [128n x 32k] per stage.
// 4 compute warps in a 2x2 grid of 64x64 warp tiles; warp 4 = TMA producer.
__global__ void __launch_bounds__(BIG_THREADS, 1)
gcn_big_gemm(const __grid_constant__ CUtensorMap tmA,
             const __grid_constant__ CUtensorMap tmB,
             const float* __restrict__ bias,
             float* __restrict__ out) {
    extern __shared__ __align__(1024) char smem[];
    const uint32_t base = smem_u32(smem);
    const int tid  = threadIdx.x;
    const int wid  = tid >> 5;
    const int lane = tid & 31;
    const int m0   = blockIdx.x * TILE_M;

    if (tid == 0) {
        for (int s = 0; s < STAGES; s++) {
            MBAR_INIT(base + SM_FULL + s * 8, 1);
            MBAR_INIT(base + SM_DONE + s * 8, 4);   // 4 consumer warps arrive
        }
    }
    __syncthreads();

    if (wid == 4) {
        // -------- TMA producer (warp 4, lane 0) --------
        if (lane == 0) {
            const CUtensorMap* pA = &tmA;
            const CUtensorMap* pB = &tmB;
            int stage = 0, ph = 1;  // first pass through each stage: no wait
            for (int i = 0; i < KITERS; i++) {
                MBAR_WAIT(base + SM_DONE + stage * 8, (uint32_t)ph);
                uint32_t full = base + SM_FULL + stage * 8;
                MBAR_EXPECT_TX(full, STAGE_TX);
                tma_2d(base + SM_A + stage * A_STAGE_BYTES, pA, i * KT, m0, full);
                tma_2d(base + SM_B + stage * B_STAGE_BYTES, pB, i * KT, 0, full);
                if (++stage == STAGES) { stage = 0; ph ^= 1; }
            }
        }
    } else {
        // -------- compute warps --------
        const int g  = lane >> 2;     // 0..7
        const int tg = lane & 3;      // 0..3
        const int wm = wid >> 1;      // 0..1
        const int wn = wid & 1;       // 0..1
        const uint32_t xorv = (uint32_t)g << 4;   // SW128 xor term (constant per thread)

        // byte offsets within a stage tile (rows are 128B)
        const uint32_t rAbase = (uint32_t)(wm * 64 + g) * 128;  // + mi*2048 + h*1024
        const uint32_t rBbase = (uint32_t)(wn * 64 + g) * 128;  // + ni*1024

        uint32_t colx[4][2];
        #pragma unroll
        for (int ks = 0; ks < 4; ks++)
            #pragma unroll
            for (int kh = 0; kh < 2; kh++)
                colx[ks][kh] = ((uint32_t)(ks * 32 + kh * 16 + tg * 4)) ^ xorv;

        float acc[4][8][4];
        #pragma unroll
        for (int mi = 0; mi < 4; mi++)
            #pragma unroll
            for (int ni = 0; ni < 8; ni++)
                #pragma unroll
                for (int q = 0; q < 4; q++) acc[mi][ni][q] = 0.0f;

        int stage = 0, ph = 0;
        for (int i = 0; i < KITERS; i++) {
            MBAR_WAIT(base + SM_FULL + stage * 8, (uint32_t)ph);
            const char* astg = smem + SM_A + stage * A_STAGE_BYTES;
            const char* bstg = smem + SM_B + stage * B_STAGE_BYTES;

            #pragma unroll
            for (int ks = 0; ks < 4; ks++) {
                uint32_t af[4][4];
                #pragma unroll
                for (int mi = 0; mi < 4; mi++)
                    #pragma unroll
                    for (int kh = 0; kh < 2; kh++)
                        #pragma unroll
                        for (int h = 0; h < 2; h++) {
                            float v = *(const float*)(astg + rAbase + mi * 2048 + h * 1024 + colx[ks][kh]);
                            af[mi][h + 2 * kh] = f2tf32(v);   // RNA round (unbiased)
                        }
                uint32_t bf[8][2];
                #pragma unroll
                for (int ni = 0; ni < 8; ni++)
                    #pragma unroll
                    for (int kh = 0; kh < 2; kh++)
                        bf[ni][kh] = *(const uint32_t*)(bstg + rBbase + ni * 1024 + colx[ks][kh]);
                #pragma unroll
                for (int mi = 0; mi < 4; mi++)
                    #pragma unroll
                    for (int ni = 0; ni < 8; ni++)
                        mma_tf32(acc[mi][ni], af[mi], bf[ni]);
            }
            if (lane == 0) MBAR_ARRIVE(base + SM_DONE + stage * 8);
            if (++stage == STAGES) { stage = 0; ph ^= 1; }
        }

        // -------- epilogue: bias + relu, write fp32 --------
        #pragma unroll
        for (int ni = 0; ni < 8; ni++) {
            const int c0 = wn * 64 + ni * 8 + tg * 2;
            const float bb0 = __ldg(&bias[c0]);
            const float bb1 = __ldg(&bias[c0 + 1]);
            #pragma unroll
            for (int mi = 0; mi < 4; mi++) {
                const int r0 = m0 + wm * 64 + mi * 16 + g;
                float2 v0, v1;
                v0.x = fmaxf(acc[mi][ni][0] + bb0, 0.0f);
                v0.y = fmaxf(acc[mi][ni][1] + bb1, 0.0f);
                v1.x = fmaxf(acc[mi][ni][2] + bb0, 0.0f);
                v1.y = fmaxf(acc[mi][ni][3] + bb1, 0.0f);
                *reinterpret_cast<float2*>(out + (size_t)r0 * HDIM + c0) = v0;
                *reinterpret_cast<float2*>(out + (size_t)(r0 + 8) * HDIM + c0) = v1;
            }
        }
    }
}

// ===================== small GEMM: outT[n][node] = sum_f in[node][f] * w[f][n] =====================
// Output is rounded to tf32 (RNA) so the big GEMM's B operand is pre-rounded.
__global__ void __launch_bounds__(256)
gcn_in_gemm(const float* __restrict__ in, const float* __restrict__ w, float* __restrict__ outT) {
    extern __shared__ float ws[];  // 128x128 fp32 = 64KB
    const int tid = threadIdx.x;
    for (int i = tid; i < (HDIM * HDIM) / 4; i += 256)
        reinterpret_cast<float4*>(ws)[i] = reinterpret_cast<const float4*>(w)[i];
    __syncthreads();

    const int ng = tid >> 3;       // 0..31
    const int cg = tid & 7;        // 0..7
    const int n0 = blockIdx.x * 128;

    float acc[4][16];
    #pragma unroll
    for (int k = 0; k < 4; k++)
        #pragma unroll
        for (int j = 0; j < 16; j++) acc[k][j] = 0.0f;

    for (int f = 0; f < HDIM; f++) {
        float a[4];
        #pragma unroll
        for (int k = 0; k < 4; k++)
            a[k] = __ldg(&in[(size_t)(n0 + ng + 32 * k) * HDIM + f]);
        const float4* wr = reinterpret_cast<const float4*>(ws + f * HDIM + cg * 16);
        float4 w0 = wr[0], w1 = wr[1], w2 = wr[2], w3 = wr[3];
        #pragma unroll
        for (int k = 0; k < 4; k++) {
            acc[k][0]  += a[k] * w0.x;  acc[k][1]  += a[k] * w0.y;
            acc[k][2]  += a[k] * w0.z;  acc[k][3]  += a[k] * w0.w;
            acc[k][4]  += a[k] * w1.x;  acc[k][5]  += a[k] * w1.y;
            acc[k][6]  += a[k] * w1.z;  acc[k][7]  += a[k] * w1.w;
            acc[k][8]  += a[k] * w2.x;  acc[k][9]  += a[k] * w2.y;
            acc[k][10] += a[k] * w2.z;  acc[k][11] += a[k] * w2.w;
            acc[k][12] += a[k] * w3.x;  acc[k][13] += a[k] * w3.y;
            acc[k][14] += a[k] * w3.z;  acc[k][15] += a[k] * w3.w;
        }
    }
    #pragma unroll
    for (int j = 0; j < 16; j++) {
        const int col = cg * 16 + j;
        #pragma unroll
        for (int k = 0; k < 4; k++) {
            uint32_t t = f2tf32(acc[k][j]);  // pre-round B operand to tf32 (RNA)
            *reinterpret_cast<uint32_t*>(&outT[(size_t)col * NNODES + n0 + ng + 32 * k]) = t;
        }
    }
}

// ===================== head: out[i][c] = b3[c] + sum_n h[i][n] * w3[n][c] =====================
__global__ void __launch_bounds__(256)
gcn_head(const float* __restrict__ h, const float* __restrict__ w3,
         const float* __restrict__ b3, float* __restrict__ out) {
    const int i = blockIdx.x * 256 + threadIdx.x;
    if (i >= NNODES) return;
    float s0 = __ldg(&b3[0]), s1 = __ldg(&b3[1]);
    const float4* hv = reinterpret_cast<const float4*>(h + (size_t)i * HDIM);
    #pragma unroll
    for (int q = 0; q < 32; q++) {
        float4 v = __ldg(&hv[q]);
        const int n = q * 4;
        s0 += v.x * __ldg(&w3[(n + 0) * 2 + 0]); s1 += v.x * __ldg(&w3[(n + 0) * 2 + 1]);
        s0 += v.y * __ldg(&w3[(n + 1) * 2 + 0]); s1 += v.y * __ldg(&w3[(n + 1) * 2 + 1]);
        s0 += v.z * __ldg(&w3[(n + 2) * 2 + 0]); s1 += v.z * __ldg(&w3[(n + 2) * 2 + 1]);
        s0 += v.w * __ldg(&w3[(n + 3) * 2 + 0]); s1 += v.w * __ldg(&w3[(n + 3) * 2 + 1]);
    }
    out[i * 2 + 0] = s0;
    out[i * 2 + 1] = s1;
}

// ===================== host =====================
typedef CUresult (*PFN_encodeTiled)(CUtensorMap*, CUtensorMapDataType, cuuint32_t, void*,
                                    const cuuint64_t*, const cuuint64_t*, const cuuint32_t*,
                                    const cuuint32_t*, CUtensorMapInterleave, CUtensorMapSwizzle,
                                    CUtensorMapL2promotion, CUtensorMapFloatOOBfill);

extern "C" void kernel_launch(void* const* d_in, const int* in_sizes, int n_in,
                              void* d_out, int out_size) {
    const float* x   = (const float*)d_in[0];
    const float* adj = (const float*)d_in[1];
    const float* w1  = (const float*)d_in[2];
    const float* b1  = (const float*)d_in[3];
    const float* w2  = (const float*)d_in[4];
    const float* b2  = (const float*)d_in[5];
    const float* w3  = (const float*)d_in[6];
    const float* b3  = (const float*)d_in[7];
    float* out = (float*)d_out;

    void* bufA = nullptr;
    void* bufH = nullptr;
    cudaGetSymbolAddress(&bufA, g_bufA);
    cudaGetSymbolAddress(&bufH, g_bufH);

    // fetch cuTensorMapEncodeTiled via runtime (no -lcuda link dependency)
    void* fn = nullptr;
    cudaDriverEntryPointQueryResult qres;
    cudaGetDriverEntryPointByVersion("cuTensorMapEncodeTiled", &fn, 12000,
                                     cudaEnableDefault, &qres);
    PFN_encodeTiled encode = (PFN_encodeTiled)fn;

    CUtensorMap tmA{}, tmB{};
    {
        cuuint64_t dims[2]   = {NNODES, NNODES};
        cuuint64_t stride[1] = {NNODES * sizeof(float)};
        cuuint32_t box[2]    = {KT, TILE_M};
        cuuint32_t es[2]     = {1, 1};
        encode(&tmA, CU_TENSOR_MAP_DATA_TYPE_FLOAT32, 2, (void*)adj, dims, stride, box, es,
               CU_TENSOR_MAP_INTERLEAVE_NONE, CU_TENSOR_MAP_SWIZZLE_128B,
               CU_TENSOR_MAP_L2_PROMOTION_L2_128B, CU_TENSOR_MAP_FLOAT_OOB_FILL_NONE);
    }
    {
        cuuint64_t dims[2]   = {NNODES, HDIM};
        cuuint64_t stride[1] = {NNODES * sizeof(float)};
        cuuint32_t box[2]    = {KT, TILE_N};
        cuuint32_t es[2]     = {1, 1};
        encode(&tmB, CU_TENSOR_MAP_DATA_TYPE_FLOAT32, 2, bufA, dims, stride, box, es,
               CU_TENSOR_MAP_INTERLEAVE_NONE, CU_TENSOR_MAP_SWIZZLE_128B,
               CU_TENSOR_MAP_L2_PROMOTION_L2_128B, CU_TENSOR_MAP_FLOAT_OOB_FILL_NONE);
    }

    cudaFuncSetAttribute(gcn_big_gemm, cudaFuncAttributeMaxDynamicSharedMemorySize, SMEM_TOTAL);
    cudaFuncSetAttribute(gcn_in_gemm, cudaFuncAttributeMaxDynamicSharedMemorySize, 65536);

    // 1) t1^T = (x @ w1)^T   (tf32-rounded)
    gcn_in_gemm<<<NNODES / 128, 256, 65536>>>(x, w1, (float*)bufA);
    // 2) h1 = relu(adj @ t1 + b1)
    gcn_big_gemm<<<NNODES / TILE_M, BIG_THREADS, SMEM_TOTAL>>>(tmA, tmB, b1, (float*)bufH);
    // 3) t2^T = (h1 @ w2)^T  (overwrites bufA; stream-ordered after step 2)
    gcn_in_gemm<<<NNODES / 128, 256, 65536>>>((const float*)bufH, w2, (float*)bufA);
    // 4) h2 = relu(adj @ t2 + b2)
    gcn_big_gemm<<<NNODES / TILE_M, BIG_THREADS, SMEM_TOTAL>>>(tmA, tmB, b2, (float*)bufH);
    // 5) out = h2 @ w3 + b3
    gcn_head<<<NNODES / 256, 256>>>((const float*)bufH, w3, b3, out);
}

// round 3
// speedup vs baseline: 1.0278x; 1.0278x over previous
#include <cuda_runtime.h>
#include <cuda.h>
#include <cstdint>

// ===================== constants =====================
#define NNODES   16384
#define HDIM     128
#define TILE_M   128
#define TILE_N   128
#define KT       32             // fp32 elems per K-stage = 128 bytes = 1 SW128 row
#define STAGES   5
#define KITERS   (NNODES / KT)  // 512

#define A_STAGE_BYTES (TILE_M * KT * 4)   // 16384
#define B_STAGE_BYTES (TILE_N * KT * 4)   // 16384
#define STAGE_TX      (A_STAGE_BYTES + B_STAGE_BYTES)

// smem layout (dynamic)
#define SM_FULL    0      // STAGES mbarriers (8B each)
#define SM_DONE    64     // STAGES mbarriers
#define SM_A       1024
#define SM_B       (SM_A + STAGES * A_STAGE_BYTES)
#define SMEM_TOTAL (SM_B + STAGES * B_STAGE_BYTES)   // 164864

#define BIG_THREADS 288   // warps 0-7 compute (2x4 grid of 64x32 tiles), warp 8 TMA

// in_gemm smem: w tile 128x128 + x tile 128x129 (pad -> conflict-free)
#define XS_PAD  129
#define IN_SMEM ((HDIM * HDIM + HDIM * XS_PAD) * 4)   // 131584

// scratch (allocation-free rule: __device__ globals)
__device__ __align__(1024) float g_bufA[128UL * 16384];   // t1^T / t2^T  [H][N]
__device__ __align__(1024) float g_bufH[16384UL * 128];   // h1 / h2      [N][H]

// ===================== PTX helpers =====================
__device__ __forceinline__ uint32_t smem_u32(const void* p) {
    uint32_t a;
    asm("{ .reg .u64 t; cvta.to.shared.u64 t, %1; cvt.u32.u64 %0, t; }" : "=r"(a) : "l"(p));
    return a;
}

#define MBAR_INIT(addr, cnt) \
    asm volatile("mbarrier.init.shared.b64 [%0], %1;" :: "r"(addr), "r"(cnt) : "memory")
#define MBAR_EXPECT_TX(addr, bytes) \
    asm volatile("mbarrier.arrive.expect_tx.shared.b64 _, [%0], %1;" :: "r"(addr), "r"(bytes) : "memory")
#define MBAR_ARRIVE(addr) \
    asm volatile("mbarrier.arrive.shared.b64 _, [%0];" :: "r"(addr) : "memory")

#define MBAR_WAIT(addr, parity) do {                                            \
    uint32_t _m = (addr), _p = (parity), _d;                                    \
    asm volatile("{\n\t.reg .pred p;\n\t"                                       \
        "mbarrier.try_wait.parity.acquire.cta.shared::cta.b64 p, [%1], %2;\n\t" \
        "selp.b32 %0, 1, 0, p;\n\t}" : "=r"(_d) : "r"(_m), "r"(_p) : "memory"); \
    if (!_d) {                                                                  \
        asm volatile("{\n\t.reg .pred P1;\n\t"                                  \
        "WL%=:\n\t"                                                             \
        "mbarrier.try_wait.parity.acquire.cta.shared::cta.b64 P1, [%0], %1, 0x989680;\n\t" \
        "@P1 bra.uni WD%=;\n\t"                                                 \
        "bra.uni WL%=;\n\t"                                                     \
        "WD%=:\n\t}" :: "r"(_m), "r"(_p) : "memory");                           \
    } } while (0)

__device__ __forceinline__ void tma_2d(uint32_t smem_dst, const CUtensorMap* map,
                                       int32_t cx, int32_t cy, uint32_t mbar) {
    asm volatile(
        "cp.async.bulk.tensor.2d.shared::cta.global.tile.mbarrier::complete_tx::bytes "
        "[%0], [%1, {%2, %3}], [%4];"
        :: "r"(smem_dst), "l"(map), "r"(cx), "r"(cy), "r"(mbar) : "memory");
}

__device__ __forceinline__ uint32_t f2tf32(float v) {
    uint32_t r;
    asm("cvt.rna.tf32.f32 %0, %1;" : "=r"(r) : "f"(v));
    return r;
}

__device__ __forceinline__ void mma_tf32(float* c, const uint32_t* a, const uint32_t* b) {
    asm volatile("mma.sync.aligned.m16n8k8.row.col.f32.tf32.tf32.f32 "
        "{%0,%1,%2,%3}, {%4,%5,%6,%7}, {%8,%9}, {%0,%1,%2,%3};"
        : "+f"(c[0]), "+f"(c[1]), "+f"(c[2]), "+f"(c[3])
        : "r"(a[0]), "r"(a[1]), "r"(a[2]), "r"(a[3]), "r"(b[0]), "r"(b[1]));
}

// ===================== big GEMM: out[m][n] = relu(bias[n] + sum_k A[m][k]*Bt[n][k]) =====================
// 8 compute warps in a 2x4 grid of 64x32 warp tiles (2 warps/SMSP to keep the
// tensor pipe fed); warp 8 = TMA producer.
__global__ void __launch_bounds__(BIG_THREADS, 1)
gcn_big_gemm(const __grid_constant__ CUtensorMap tmA,
             const __grid_constant__ CUtensorMap tmB,
             const float* __restrict__ bias,
             float* __restrict__ out) {
    extern __shared__ __align__(1024) char smem[];
    const uint32_t base = smem_u32(smem);
    const int tid  = threadIdx.x;
    const int wid  = tid >> 5;
    const int lane = tid & 31;
    const int m0   = blockIdx.x * TILE_M;

    if (tid == 0) {
        for (int s = 0; s < STAGES; s++) {
            MBAR_INIT(base + SM_FULL + s * 8, 1);
            MBAR_INIT(base + SM_DONE + s * 8, 8);   // 8 consumer warps arrive
        }
    }
    __syncthreads();

    if (wid == 8) {
        // -------- TMA producer (warp 8, lane 0) --------
        if (lane == 0) {
            const CUtensorMap* pA = &tmA;
            const CUtensorMap* pB = &tmB;
            int stage = 0, ph = 1;  // first pass through each stage: no wait
            for (int i = 0; i < KITERS; i++) {
                MBAR_WAIT(base + SM_DONE + stage * 8, (uint32_t)ph);
                uint32_t full = base + SM_FULL + stage * 8;
                MBAR_EXPECT_TX(full, STAGE_TX);
                tma_2d(base + SM_A + stage * A_STAGE_BYTES, pA, i * KT, m0, full);
                tma_2d(base + SM_B + stage * B_STAGE_BYTES, pB, i * KT, 0, full);
                if (++stage == STAGES) { stage = 0; ph ^= 1; }
            }
        }
    } else {
        // -------- compute warps --------
        const int g  = lane >> 2;     // 0..7
        const int tg = lane & 3;      // 0..3
        const int wm = wid >> 2;      // 0..1  (m: 64-row band)
        const int wn = wid & 3;       // 0..3  (n: 32-col band)
        const uint32_t xorv = (uint32_t)g << 4;   // SW128 xor term (constant per thread)

        // byte offsets within a stage tile (rows are 128B)
        const uint32_t rAbase = (uint32_t)(wm * 64 + g) * 128;  // + mi*2048 + h*1024
        const uint32_t rBbase = (uint32_t)(wn * 32 + g) * 128;  // + ni*1024

        uint32_t colx[4][2];
        #pragma unroll
        for (int ks = 0; ks < 4; ks++)
            #pragma unroll
            for (int kh = 0; kh < 2; kh++)
                colx[ks][kh] = ((uint32_t)(ks * 32 + kh * 16 + tg * 4)) ^ xorv;

        float acc[4][4][4];
        #pragma unroll
        for (int mi = 0; mi < 4; mi++)
            #pragma unroll
            for (int ni = 0; ni < 4; ni++)
                #pragma unroll
                for (int q = 0; q < 4; q++) acc[mi][ni][q] = 0.0f;

        int stage = 0, ph = 0;
        for (int i = 0; i < KITERS; i++) {
            MBAR_WAIT(base + SM_FULL + stage * 8, (uint32_t)ph);
            const char* astg = smem + SM_A + stage * A_STAGE_BYTES;
            const char* bstg = smem + SM_B + stage * B_STAGE_BYTES;

            #pragma unroll
            for (int ks = 0; ks < 4; ks++) {
                uint32_t af[4][4];
                #pragma unroll
                for (int mi = 0; mi < 4; mi++)
                    #pragma unroll
                    for (int kh = 0; kh < 2; kh++)
                        #pragma unroll
                        for (int h = 0; h < 2; h++) {
                            float v = *(const float*)(astg + rAbase + mi * 2048 + h * 1024 + colx[ks][kh]);
                            af[mi][h + 2 * kh] = f2tf32(v);   // RNA round (unbiased)
                        }
                uint32_t bf[4][2];
                #pragma unroll
                for (int ni = 0; ni < 4; ni++)
                    #pragma unroll
                    for (int kh = 0; kh < 2; kh++)
                        bf[ni][kh] = *(const uint32_t*)(bstg + rBbase + ni * 1024 + colx[ks][kh]);
                #pragma unroll
                for (int mi = 0; mi < 4; mi++)
                    #pragma unroll
                    for (int ni = 0; ni < 4; ni++)
                        mma_tf32(acc[mi][ni], af[mi], bf[ni]);
            }
            if (lane == 0) MBAR_ARRIVE(base + SM_DONE + stage * 8);
            if (++stage == STAGES) { stage = 0; ph ^= 1; }
        }

        // -------- epilogue: bias + relu, write fp32 --------
        #pragma unroll
        for (int ni = 0; ni < 4; ni++) {
            const int c0 = wn * 32 + ni * 8 + tg * 2;
            const float bb0 = __ldg(&bias[c0]);
            const float bb1 = __ldg(&bias[c0 + 1]);
            #pragma unroll
            for (int mi = 0; mi < 4; mi++) {
                const int r0 = m0 + wm * 64 + mi * 16 + g;
                float2 v0, v1;
                v0.x = fmaxf(acc[mi][ni][0] + bb0, 0.0f);
                v0.y = fmaxf(acc[mi][ni][1] + bb1, 0.0f);
                v1.x = fmaxf(acc[mi][ni][2] + bb0, 0.0f);
                v1.y = fmaxf(acc[mi][ni][3] + bb1, 0.0f);
                *reinterpret_cast<float2*>(out + (size_t)r0 * HDIM + c0) = v0;
                *reinterpret_cast<float2*>(out + (size_t)(r0 + 8) * HDIM + c0) = v1;
            }
        }
    }
}

// ===================== small GEMM: outT[n][node] = sum_f in[node][f] * w[f][n] =====================
// Both operands staged in smem; warp cg handles 16 output cols, lane = node,
// 4 nodes per thread. Output rounded to tf32 (RNA) = pre-rounded B for big GEMM.
__global__ void __launch_bounds__(256)
gcn_in_gemm(const float* __restrict__ in, const float* __restrict__ w, float* __restrict__ outT) {
    extern __shared__ float sm[];
    float* ws = sm;                       // [128][128]
    float* xs = sm + HDIM * HDIM;         // [128][129] padded
    const int tid = threadIdx.x;
    const int n0 = blockIdx.x * 128;

    for (int i = tid; i < (HDIM * HDIM) / 4; i += 256)
        reinterpret_cast<float4*>(ws)[i] = reinterpret_cast<const float4*>(w)[i];
    // coalesced load of x tile into padded smem (conflict-free later reads)
    {
        const int col = tid & 127;
        const int r0  = tid >> 7;          // 0..1
        for (int r = r0; r < 128; r += 2)
            xs[r * XS_PAD + col] = in[(size_t)(n0 + r) * HDIM + col];
    }
    __syncthreads();

    const int cg   = tid >> 5;    // warp id: 16-col group
    const int lane = tid & 31;

    float acc[4][16];
    #pragma unroll
    for (int k = 0; k < 4; k++)
        #pragma unroll
        for (int j = 0; j < 16; j++) acc[k][j] = 0.0f;

    #pragma unroll 4
    for (int f = 0; f < HDIM; f++) {
        float a[4];
        #pragma unroll
        for (int k = 0; k < 4; k++)
            a[k] = xs[(lane + 32 * k) * XS_PAD + f];
        const float4* wr = reinterpret_cast<const float4*>(ws + f * HDIM + cg * 16);
        float4 w0 = wr[0], w1 = wr[1], w2 = wr[2], w3 = wr[3];
        #pragma unroll
        for (int k = 0; k < 4; k++) {
            acc[k][0]  += a[k] * w0.x;  acc[k][1]  += a[k] * w0.y;
            acc[k][2]  += a[k] * w0.z;  acc[k][3]  += a[k] * w0.w;
            acc[k][4]  += a[k] * w1.x;  acc[k][5]  += a[k] * w1.y;
            acc[k][6]  += a[k] * w1.z;  acc[k][7]  += a[k] * w1.w;
            acc[k][8]  += a[k] * w2.x;  acc[k][9]  += a[k] * w2.y;
            acc[k][10] += a[k] * w2.z;  acc[k][11] += a[k] * w2.w;
            acc[k][12] += a[k] * w3.x;  acc[k][13] += a[k] * w3.y;
            acc[k][14] += a[k] * w3.z;  acc[k][15] += a[k] * w3.w;
        }
    }
    #pragma unroll
    for (int j = 0; j < 16; j++) {
        const int col = cg * 16 + j;
        #pragma unroll
        for (int k = 0; k < 4; k++) {
            uint32_t t = f2tf32(acc[k][j]);  // pre-round B operand to tf32 (RNA)
            *reinterpret_cast<uint32_t*>(&outT[(size_t)col * NNODES + n0 + lane + 32 * k]) = t;
        }
    }
}

// ===================== head: out[i][c] = b3[c] + sum_n h[i][n] * w3[n][c] =====================
__global__ void __launch_bounds__(256)
gcn_head(const float* __restrict__ h, const float* __restrict__ w3,
         const float* __restrict__ b3, float* __restrict__ out) {
    const int i = blockIdx.x * 256 + threadIdx.x;
    if (i >= NNODES) return;
    float s0 = __ldg(&b3[0]), s1 = __ldg(&b3[1]);
    const float4* hv = reinterpret_cast<const float4*>(h + (size_t)i * HDIM);
    #pragma unroll
    for (int q = 0; q < 32; q++) {
        float4 v = __ldg(&hv[q]);
        const int n = q * 4;
        s0 += v.x * __ldg(&w3[(n + 0) * 2 + 0]); s1 += v.x * __ldg(&w3[(n + 0) * 2 + 1]);
        s0 += v.y * __ldg(&w3[(n + 1) * 2 + 0]); s1 += v.y * __ldg(&w3[(n + 1) * 2 + 1]);
        s0 += v.z * __ldg(&w3[(n + 2) * 2 + 0]); s1 += v.z * __ldg(&w3[(n + 2) * 2 + 1]);
        s0 += v.w * __ldg(&w3[(n + 3) * 2 + 0]); s1 += v.w * __ldg(&w3[(n + 3) * 2 + 1]);
    }
    out[i * 2 + 0] = s0;
    out[i * 2 + 1] = s1;
}

// ===================== host =====================
typedef CUresult (*PFN_encodeTiled)(CUtensorMap*, CUtensorMapDataType, cuuint32_t, void*,
                                    const cuuint64_t*, const cuuint64_t*, const cuuint32_t*,
                                    const cuuint32_t*, CUtensorMapInterleave, CUtensorMapSwizzle,
                                    CUtensorMapL2promotion, CUtensorMapFloatOOBfill);

extern "C" void kernel_launch(void* const* d_in, const int* in_sizes, int n_in,
                              void* d_out, int out_size) {
    const float* x   = (const float*)d_in[0];
    const float* adj = (const float*)d_in[1];
    const float* w1  = (const float*)d_in[2];
    const float* b1  = (const float*)d_in[3];
    const float* w2  = (const float*)d_in[4];
    const float* b2  = (const float*)d_in[5];
    const float* w3  = (const float*)d_in[6];
    const float* b3  = (const float*)d_in[7];
    float* out = (float*)d_out;

    void* bufA = nullptr;
    void* bufH = nullptr;
    cudaGetSymbolAddress(&bufA, g_bufA);
    cudaGetSymbolAddress(&bufH, g_bufH);

    // fetch cuTensorMapEncodeTiled via runtime (no -lcuda link dependency)
    void* fn = nullptr;
    cudaDriverEntryPointQueryResult qres;
    cudaGetDriverEntryPointByVersion("cuTensorMapEncodeTiled", &fn, 12000,
                                     cudaEnableDefault, &qres);
    PFN_encodeTiled encode = (PFN_encodeTiled)fn;

    CUtensorMap tmA{}, tmB{};
    {
        cuuint64_t dims[2]   = {NNODES, NNODES};
        cuuint64_t stride[1] = {NNODES * sizeof(float)};
        cuuint32_t box[2]    = {KT, TILE_M};
        cuuint32_t es[2]     = {1, 1};
        encode(&tmA, CU_TENSOR_MAP_DATA_TYPE_FLOAT32, 2, (void*)adj, dims, stride, box, es,
               CU_TENSOR_MAP_INTERLEAVE_NONE, CU_TENSOR_MAP_SWIZZLE_128B,
               CU_TENSOR_MAP_L2_PROMOTION_L2_128B, CU_TENSOR_MAP_FLOAT_OOB_FILL_NONE);
    }
    {
        cuuint64_t dims[2]   = {NNODES, HDIM};
        cuuint64_t stride[1] = {NNODES * sizeof(float)};
        cuuint32_t box[2]    = {KT, TILE_N};
        cuuint32_t es[2]     = {1, 1};
        encode(&tmB, CU_TENSOR_MAP_DATA_TYPE_FLOAT32, 2, bufA, dims, stride, box, es,
               CU_TENSOR_MAP_INTERLEAVE_NONE, CU_TENSOR_MAP_SWIZZLE_128B,
               CU_TENSOR_MAP_L2_PROMOTION_L2_128B, CU_TENSOR_MAP_FLOAT_OOB_FILL_NONE);
    }

    cudaFuncSetAttribute(gcn_big_gemm, cudaFuncAttributeMaxDynamicSharedMemorySize, SMEM_TOTAL);
    cudaFuncSetAttribute(gcn_in_gemm, cudaFuncAttributeMaxDynamicSharedMemorySize, IN_SMEM);

    // 1) t1^T = (x @ w1)^T   (tf32-rounded)
    gcn_in_gemm<<<NNODES / 128, 256, IN_SMEM>>>(x, w1, (float*)bufA);
    // 2) h1 = relu(adj @ t1 + b1)
    gcn_big_gemm<<<NNODES / TILE_M, BIG_THREADS, SMEM_TOTAL>>>(tmA, tmB, b1, (float*)bufH);
    // 3) t2^T = (h1 @ w2)^T  (overwrites bufA; stream-ordered after step 2)
    gcn_in_gemm<<<NNODES / 128, 256, IN_SMEM>>>((const float*)bufH, w2, (float*)bufA);
    // 4) h2 = relu(adj @ t2 + b2)
    gcn_big_gemm<<<NNODES / TILE_M, BIG_THREADS, SMEM_TOTAL>>>(tmA, tmB, b2, (float*)bufH);
    // 5) out = h2 @ w3 + b3
    gcn_head<<<NNODES / 256, 256>>>((const float*)bufH, w3, b3, out);
}

// round 4
// speedup vs baseline: 1.1110x; 1.0810x over previous
#include <cuda_runtime.h>
#include <cuda.h>
#include <cstdint>

// ===================== constants =====================
#define NNODES   16384
#define HDIM     128
#define TILE_M   128
#define TILE_N   128
#define KSUPER   64             // fp32 elems of K per super-stage (4 TMA boxes)
#define SSTAGES  3
#define SITERS   (NNODES / KSUPER)   // 256

#define A_SS_BYTES (TILE_M * KSUPER * 4)   // 32768
#define B_SS_BYTES (TILE_N * KSUPER * 4)   // 32768
#define SS_TX      (A_SS_BYTES + B_SS_BYTES)  // 65536

// smem layout (dynamic)
#define SM_FULL    0      // SSTAGES mbarriers (8B each)
#define SM_DONE    64     // SSTAGES mbarriers
#define SM_A       1024
#define SM_B       (SM_A + SSTAGES * A_SS_BYTES)     // 99328
#define SMEM_TOTAL (SM_B + SSTAGES * B_SS_BYTES)     // 197632

#define BIG_THREADS 160   // warps 0-3 compute (2x2 of 64x64), warp 4 TMA producer

// in_gemm smem: w tile 128x128 + x tile 128x129 (pad -> conflict-free)
#define XS_PAD  129
#define IN_SMEM ((HDIM * HDIM + HDIM * XS_PAD) * 4)   // 131584

// scratch (allocation-free rule: __device__ globals)
__device__ __align__(1024) float g_bufA[128UL * 16384];   // t1^T / t2^T  [H][N]
__device__ __align__(1024) float g_bufH[16384UL * 128];   // h1 / h2      [N][H]

// ===================== PTX helpers =====================
__device__ __forceinline__ uint32_t smem_u32(const void* p) {
    uint32_t a;
    asm("{ .reg .u64 t; cvta.to.shared.u64 t, %1; cvt.u32.u64 %0, t; }" : "=r"(a) : "l"(p));
    return a;
}

#define MBAR_INIT(addr, cnt) \
    asm volatile("mbarrier.init.shared.b64 [%0], %1;" :: "r"(addr), "r"(cnt) : "memory")
#define MBAR_EXPECT_TX(addr, bytes) \
    asm volatile("mbarrier.arrive.expect_tx.shared.b64 _, [%0], %1;" :: "r"(addr), "r"(bytes) : "memory")
#define MBAR_ARRIVE(addr) \
    asm volatile("mbarrier.arrive.shared.b64 _, [%0];" :: "r"(addr) : "memory")

#define MBAR_WAIT(addr, parity) do {                                            \
    uint32_t _m = (addr), _p = (parity), _d;                                    \
    asm volatile("{\n\t.reg .pred p;\n\t"                                       \
        "mbarrier.try_wait.parity.acquire.cta.shared::cta.b64 p, [%1], %2;\n\t" \
        "selp.b32 %0, 1, 0, p;\n\t}" : "=r"(_d) : "r"(_m), "r"(_p) : "memory"); \
    if (!_d) {                                                                  \
        asm volatile("{\n\t.reg .pred P1;\n\t"                                  \
        "WL%=:\n\t"                                                             \
        "mbarrier.try_wait.parity.acquire.cta.shared::cta.b64 P1, [%0], %1, 0x989680;\n\t" \
        "@P1 bra.uni WD%=;\n\t"                                                 \
        "bra.uni WL%=;\n\t"                                                     \
        "WD%=:\n\t}" :: "r"(_m), "r"(_p) : "memory");                           \
    } } while (0)

__device__ __forceinline__ void tma_2d(uint32_t smem_dst, const CUtensorMap* map,
                                       int32_t cx, int32_t cy, uint32_t mbar) {
    asm volatile(
        "cp.async.bulk.tensor.2d.shared::cta.global.tile.mbarrier::complete_tx::bytes "
        "[%0], [%1, {%2, %3}], [%4];"
        :: "r"(smem_dst), "l"(map), "r"(cx), "r"(cy), "r"(mbar) : "memory");
}

__device__ __forceinline__ uint32_t f2tf32(float v) {
    uint32_t r;
    asm("cvt.rna.tf32.f32 %0, %1;" : "=r"(r) : "f"(v));
    return r;
}

__device__ __forceinline__ void mma_tf32(float* c, const uint32_t* a, const uint32_t* b) {
    asm volatile("mma.sync.aligned.m16n8k8.row.col.f32.tf32.tf32.f32 "
        "{%0,%1,%2,%3}, {%4,%5,%6,%7}, {%8,%9}, {%0,%1,%2,%3};"
        : "+f"(c[0]), "+f"(c[1]), "+f"(c[2]), "+f"(c[3])
        : "r"(a[0]), "r"(a[1]), "r"(a[2]), "r"(a[3]), "r"(b[0]), "r"(b[1]));
}

// ===================== big GEMM =====================
// out[m][n] = relu(bias[n] + sum_k A[m][k]*Bt[n][k])
// 4 compute warps (2x2 of 64x64 warp tiles), warp 4 = TMA producer.
// Super-stages of K=64 (4 TMA boxes / 1 barrier). Double-buffered register
// fragments: k-block kb+1 loads issue before kb's MMAs.

struct FragA { uint32_t v[4][4]; };   // [mi][reg]
struct FragB { uint32_t v[8][2]; };   // [ni][reg]

__device__ __forceinline__ void load_frags(FragA& fa, FragB& fb,
                                           const char* abase, const char* bbase,
                                           uint32_t rAbase, uint32_t rBbase,
                                           const uint32_t* cx /*[2]*/) {
    #pragma unroll
    for (int mi = 0; mi < 4; mi++)
        #pragma unroll
        for (int kh = 0; kh < 2; kh++)
            #pragma unroll
            for (int h = 0; h < 2; h++) {
                float v = *(const float*)(abase + rAbase + mi * 2048 + h * 1024 + cx[kh]);
                fa.v[mi][h + 2 * kh] = f2tf32(v);
            }
    #pragma unroll
    for (int ni = 0; ni < 8; ni++)
        #pragma unroll
        for (int kh = 0; kh < 2; kh++)
            fb.v[ni][kh] = *(const uint32_t*)(bbase + rBbase + ni * 1024 + cx[kh]);
}

__device__ __forceinline__ void mma_block(float acc[4][8][4], const FragA& fa, const FragB& fb) {
    #pragma unroll
    for (int mi = 0; mi < 4; mi++)
        #pragma unroll
        for (int ni = 0; ni < 8; ni++)
            mma_tf32(acc[mi][ni], fa.v[mi], fb.v[ni]);
}

__global__ void __launch_bounds__(BIG_THREADS, 1)
gcn_big_gemm(const __grid_constant__ CUtensorMap tmA,
             const __grid_constant__ CUtensorMap tmB,
             const float* __restrict__ bias,
             float* __restrict__ out) {
    extern __shared__ __align__(1024) char smem[];
    const uint32_t base = smem_u32(smem);
    const int tid  = threadIdx.x;
    const int wid  = tid >> 5;
    const int lane = tid & 31;
    const int m0   = blockIdx.x * TILE_M;

    if (tid == 0) {
        for (int s = 0; s < SSTAGES; s++) {
            MBAR_INIT(base + SM_FULL + s * 8, 1);
            MBAR_INIT(base + SM_DONE + s * 8, 4);
        }
    }
    __syncthreads();

    if (wid == 4) {
        // -------- TMA producer --------
        if (lane == 0) {
            const CUtensorMap* pA = &tmA;
            const CUtensorMap* pB = &tmB;
            int ss = 0, ph = 1;
            for (int i = 0; i < SITERS; i++) {
                MBAR_WAIT(base + SM_DONE + ss * 8, (uint32_t)ph);
                uint32_t full = base + SM_FULL + ss * 8;
                MBAR_EXPECT_TX(full, SS_TX);
                uint32_t aslot = base + SM_A + ss * A_SS_BYTES;
                uint32_t bslot = base + SM_B + ss * B_SS_BYTES;
                int k0 = i * KSUPER;
                tma_2d(aslot,         pA, k0,      m0, full);
                tma_2d(aslot + 16384, pA, k0 + 32, m0, full);
                tma_2d(bslot,         pB, k0,      0,  full);
                tma_2d(bslot + 16384, pB, k0 + 32, 0,  full);
                if (++ss == SSTAGES) { ss = 0; ph ^= 1; }
            }
        }
    } else {
        // -------- compute warps --------
        const int g  = lane >> 2;
        const int tg = lane & 3;
        const int wm = wid >> 1;      // 0..1
        const int wn = wid & 1;       // 0..1
        const uint32_t xorv = (uint32_t)g << 4;

        const uint32_t rAbase = (uint32_t)(wm * 64 + g) * 128;
        const uint32_t rBbase = (uint32_t)(wn * 64 + g) * 128;

        // colx[ksub][kh]: byte col within a 32-float half, SW128-xored
        uint32_t colx[4][2];
        #pragma unroll
        for (int ks = 0; ks < 4; ks++)
            #pragma unroll
            for (int kh = 0; kh < 2; kh++)
                colx[ks][kh] = ((uint32_t)(ks * 32 + kh * 16 + tg * 4)) ^ xorv;

        float acc[4][8][4];
        #pragma unroll
        for (int mi = 0; mi < 4; mi++)
            #pragma unroll
            for (int ni = 0; ni < 8; ni++)
                #pragma unroll
                for (int q = 0; q < 4; q++) acc[mi][ni][q] = 0.0f;

        FragA afA, afB2;
        FragB bfA, bfB2;

        int ss = 0, ph = 0;
        const char* aslot = smem + SM_A;
        const char* bslot = smem + SM_B;

        MBAR_WAIT(base + SM_FULL, 0u);
        load_frags(afA, bfA, aslot, bslot, rAbase, rBbase, colx[0]);

        for (int i = 0; i < SITERS; i++) {
            // kb = 0..7 ; khalf = kb>>2 ; ksub = kb&3 ; buffers alternate
            #pragma unroll
            for (int kb = 0; kb < 8; kb++) {
                const int nkb   = kb + 1;
                if (kb < 7) {
                    const char* ah = aslot + ((nkb >> 2) ? 16384 : 0);
                    const char* bh = bslot + ((nkb >> 2) ? 16384 : 0);
                    if ((kb & 1) == 0) {
                        load_frags(afB2, bfB2, ah, bh, rAbase, rBbase, colx[nkb & 3]);
                        mma_block(acc, afA, bfA);
                    } else {
                        load_frags(afA, bfA, ah, bh, rAbase, rBbase, colx[nkb & 3]);
                        mma_block(acc, afB2, bfB2);
                    }
                } else {
                    // kb == 7 : cur buffer is afB2/bfB2 (7 is odd)
                    mma_block(acc, afB2, bfB2);   // forces LDS drain before arrive
                    if (lane == 0) MBAR_ARRIVE(base + SM_DONE + ss * 8);
                    // advance slot
                    int ssn = ss + 1, phn = ph;
                    if (ssn == SSTAGES) { ssn = 0; phn ^= 1; }
                    if (i < SITERS - 1) {
                        MBAR_WAIT(base + SM_FULL + ssn * 8, (uint32_t)phn);
                        const char* an = smem + SM_A + ssn * A_SS_BYTES;
                        const char* bn = smem + SM_B + ssn * B_SS_BYTES;
                        load_frags(afA, bfA, an, bn, rAbase, rBbase, colx[0]);
                        aslot = an; bslot = bn;
                    }
                    ss = ssn; ph = phn;
                }
            }
        }

        // -------- epilogue: bias + relu, write fp32 --------
        #pragma unroll
        for (int ni = 0; ni < 8; ni++) {
            const int c0 = wn * 64 + ni * 8 + tg * 2;
            const float bb0 = __ldg(&bias[c0]);
            const float bb1 = __ldg(&bias[c0 + 1]);
            #pragma unroll
            for (int mi = 0; mi < 4; mi++) {
                const int r0 = m0 + wm * 64 + mi * 16 + g;
                float2 v0, v1;
                v0.x = fmaxf(acc[mi][ni][0] + bb0, 0.0f);
                v0.y = fmaxf(acc[mi][ni][1] + bb1, 0.0f);
                v1.x = fmaxf(acc[mi][ni][2] + bb0, 0.0f);
                v1.y = fmaxf(acc[mi][ni][3] + bb1, 0.0f);
                *reinterpret_cast<float2*>(out + (size_t)r0 * HDIM + c0) = v0;
                *reinterpret_cast<float2*>(out + (size_t)(r0 + 8) * HDIM + c0) = v1;
            }
        }
    }
}

// ===================== small GEMM: outT[n][node] = sum_f in[node][f] * w[f][n] =====================
__global__ void __launch_bounds__(256)
gcn_in_gemm(const float* __restrict__ in, const float* __restrict__ w, float* __restrict__ outT) {
    extern __shared__ float sm[];
    float* ws = sm;                       // [128][128]
    float* xs = sm + HDIM * HDIM;         // [128][129] padded
    const int tid = threadIdx.x;
    const int n0 = blockIdx.x * 128;

    for (int i = tid; i < (HDIM * HDIM) / 4; i += 256)
        reinterpret_cast<float4*>(ws)[i] = reinterpret_cast<const float4*>(w)[i];
    {
        const int col = tid & 127;
        const int r0  = tid >> 7;
        for (int r = r0; r < 128; r += 2)
            xs[r * XS_PAD + col] = in[(size_t)(n0 + r) * HDIM + col];
    }
    __syncthreads();

    const int cg   = tid >> 5;
    const int lane = tid & 31;

    float acc[4][16];
    #pragma unroll
    for (int k = 0; k < 4; k++)
        #pragma unroll
        for (int j = 0; j < 16; j++) acc[k][j] = 0.0f;

    #pragma unroll 4
    for (int f = 0; f < HDIM; f++) {
        float a[4];
        #pragma unroll
        for (int k = 0; k < 4; k++)
            a[k] = xs[(lane + 32 * k) * XS_PAD + f];
        const float4* wr = reinterpret_cast<const float4*>(ws + f * HDIM + cg * 16);
        float4 w0 = wr[0], w1 = wr[1], w2 = wr[2], w3 = wr[3];
        #pragma unroll
        for (int k = 0; k < 4; k++) {
            acc[k][0]  += a[k] * w0.x;  acc[k][1]  += a[k] * w0.y;
            acc[k][2]  += a[k] * w0.z;  acc[k][3]  += a[k] * w0.w;
            acc[k][4]  += a[k] * w1.x;  acc[k][5]  += a[k] * w1.y;
            acc[k][6]  += a[k] * w1.z;  acc[k][7]  += a[k] * w1.w;
            acc[k][8]  += a[k] * w2.x;  acc[k][9]  += a[k] * w2.y;
            acc[k][10] += a[k] * w2.z;  acc[k][11] += a[k] * w2.w;
            acc[k][12] += a[k] * w3.x;  acc[k][13] += a[k] * w3.y;
            acc[k][14] += a[k] * w3.z;  acc[k][15] += a[k] * w3.w;
        }
    }
    #pragma unroll
    for (int j = 0; j < 16; j++) {
        const int col = cg * 16 + j;
        #pragma unroll
        for (int k = 0; k < 4; k++) {
            uint32_t t = f2tf32(acc[k][j]);
            *reinterpret_cast<uint32_t*>(&outT[(size_t)col * NNODES + n0 + lane + 32 * k]) = t;
        }
    }
}

// ===================== head: out[i][c] = b3[c] + sum_n h[i][n] * w3[n][c] =====================
__global__ void __launch_bounds__(256)
gcn_head(const float* __restrict__ h, const float* __restrict__ w3,
         const float* __restrict__ b3, float* __restrict__ out) {
    const int i = blockIdx.x * 256 + threadIdx.x;
    if (i >= NNODES) return;
    float s0 = __ldg(&b3[0]), s1 = __ldg(&b3[1]);
    const float4* hv = reinterpret_cast<const float4*>(h + (size_t)i * HDIM);
    #pragma unroll
    for (int q = 0; q < 32; q++) {
        float4 v = __ldg(&hv[q]);
        const int n = q * 4;
        s0 += v.x * __ldg(&w3[(n + 0) * 2 + 0]); s1 += v.x * __ldg(&w3[(n + 0) * 2 + 1]);
        s0 += v.y * __ldg(&w3[(n + 1) * 2 + 0]); s1 += v.y * __ldg(&w3[(n + 1) * 2 + 1]);
        s0 += v.z * __ldg(&w3[(n + 2) * 2 + 0]); s1 += v.z * __ldg(&w3[(n + 2) * 2 + 1]);
        s0 += v.w * __ldg(&w3[(n + 3) * 2 + 0]); s1 += v.w * __ldg(&w3[(n + 3) * 2 + 1]);
    }
    out[i * 2 + 0] = s0;
    out[i * 2 + 1] = s1;
}

// ===================== host =====================
typedef CUresult (*PFN_encodeTiled)(CUtensorMap*, CUtensorMapDataType, cuuint32_t, void*,
                                    const cuuint64_t*, const cuuint64_t*, const cuuint32_t*,
                                    const cuuint32_t*, CUtensorMapInterleave, CUtensorMapSwizzle,
                                    CUtensorMapL2promotion, CUtensorMapFloatOOBfill);

extern "C" void kernel_launch(void* const* d_in, const int* in_sizes, int n_in,
                              void* d_out, int out_size) {
    const float* x   = (const float*)d_in[0];
    const float* adj = (const float*)d_in[1];
    const float* w1  = (const float*)d_in[2];
    const float* b1  = (const float*)d_in[3];
    const float* w2  = (const float*)d_in[4];
    const float* b2  = (const float*)d_in[5];
    const float* w3  = (const float*)d_in[6];
    const float* b3  = (const float*)d_in[7];
    float* out = (float*)d_out;

    void* bufA = nullptr;
    void* bufH = nullptr;
    cudaGetSymbolAddress(&bufA, g_bufA);
    cudaGetSymbolAddress(&bufH, g_bufH);

    void* fn = nullptr;
    cudaDriverEntryPointQueryResult qres;
    cudaGetDriverEntryPointByVersion("cuTensorMapEncodeTiled", &fn, 12000,
                                     cudaEnableDefault, &qres);
    PFN_encodeTiled encode = (PFN_encodeTiled)fn;

    CUtensorMap tmA{}, tmB{};
    {
        cuuint64_t dims[2]   = {NNODES, NNODES};
        cuuint64_t stride[1] = {NNODES * sizeof(float)};
        cuuint32_t box[2]    = {32, TILE_M};
        cuuint32_t es[2]     = {1, 1};
        encode(&tmA, CU_TENSOR_MAP_DATA_TYPE_FLOAT32, 2, (void*)adj, dims, stride, box, es,
               CU_TENSOR_MAP_INTERLEAVE_NONE, CU_TENSOR_MAP_SWIZZLE_128B,
               CU_TENSOR_MAP_L2_PROMOTION_L2_128B, CU_TENSOR_MAP_FLOAT_OOB_FILL_NONE);
    }
    {
        cuuint64_t dims[2]   = {NNODES, HDIM};
        cuuint64_t stride[1] = {NNODES * sizeof(float)};
        cuuint32_t box[2]    = {32, TILE_N};
        cuuint32_t es[2]     = {1, 1};
        encode(&tmB, CU_TENSOR_MAP_DATA_TYPE_FLOAT32, 2, bufA, dims, stride, box, es,
               CU_TENSOR_MAP_INTERLEAVE_NONE, CU_TENSOR_MAP_SWIZZLE_128B,
               CU_TENSOR_MAP_L2_PROMOTION_L2_128B, CU_TENSOR_MAP_FLOAT_OOB_FILL_NONE);
    }

    cudaFuncSetAttribute(gcn_big_gemm, cudaFuncAttributeMaxDynamicSharedMemorySize, SMEM_TOTAL);
    cudaFuncSetAttribute(gcn_in_gemm, cudaFuncAttributeMaxDynamicSharedMemorySize, IN_SMEM);

    gcn_in_gemm<<<NNODES / 128, 256, IN_SMEM>>>(x, w1, (float*)bufA);
    gcn_big_gemm<<<NNODES / TILE_M, BIG_THREADS, SMEM_TOTAL>>>(tmA, tmB, b1, (float*)bufH);
    gcn_in_gemm<<<NNODES / 128, 256, IN_SMEM>>>((const float*)bufH, w2, (float*)bufA);
    gcn_big_gemm<<<NNODES / TILE_M, BIG_THREADS, SMEM_TOTAL>>>(tmA, tmB, b2, (float*)bufH);
    gcn_head<<<NNODES / 256, 256>>>((const float*)bufH, w3, b3, out);
}

// round 5
// speedup vs baseline: 1.1589x; 1.0430x over previous
#include <cuda_runtime.h>
#include <cuda.h>
#include <cstdint>

// ===================== constants =====================
#define NNODES   16384
#define HDIM     128
#define TILE_M   128
#define TILE_N   128
#define KSUPER   64             // fp32 elems of K per super-stage (4 TMA boxes)
#define SSTAGES  3
#define SITERS   (NNODES / KSUPER)   // 256

#define A_SS_BYTES (TILE_M * KSUPER * 4)   // 32768
#define B_SS_BYTES (TILE_N * KSUPER * 4)   // 32768
#define SS_TX      (A_SS_BYTES + B_SS_BYTES)  // 65536

// smem layout (dynamic)
#define SM_FULL    0      // SSTAGES mbarriers (8B each)
#define SM_DONE    64     // SSTAGES mbarriers
#define SM_A       1024
#define SM_B       (SM_A + SSTAGES * A_SS_BYTES)
#define SMEM_TOTAL (SM_B + SSTAGES * B_SS_BYTES)     // 197632

#define BIG_THREADS 288   // warps 0-7 compute (4x2 grid of 32x64 tiles), warp 8 TMA

// in_gemm smem: w tile 128x128 + x tile 128x129 (pad -> conflict-free)
#define XS_PAD  129
#define IN_SMEM ((HDIM * HDIM + HDIM * XS_PAD) * 4)   // 131584

// scratch (allocation-free rule: __device__ globals)
__device__ __align__(1024) float g_bufA[128UL * 16384];   // t1^T / t2^T  [H][N]
__device__ __align__(1024) float g_bufH[16384UL * 128];   // h1 / h2      [N][H]

// ===================== PTX helpers =====================
__device__ __forceinline__ uint32_t smem_u32(const void* p) {
    uint32_t a;
    asm("{ .reg .u64 t; cvta.to.shared.u64 t, %1; cvt.u32.u64 %0, t; }" : "=r"(a) : "l"(p));
    return a;
}

#define MBAR_INIT(addr, cnt) \
    asm volatile("mbarrier.init.shared.b64 [%0], %1;" :: "r"(addr), "r"(cnt) : "memory")
#define MBAR_EXPECT_TX(addr, bytes) \
    asm volatile("mbarrier.arrive.expect_tx.shared.b64 _, [%0], %1;" :: "r"(addr), "r"(bytes) : "memory")
#define MBAR_ARRIVE(addr) \
    asm volatile("mbarrier.arrive.shared.b64 _, [%0];" :: "r"(addr) : "memory")

#define MBAR_WAIT(addr, parity) do {                                            \
    uint32_t _m = (addr), _p = (parity), _d;                                    \
    asm volatile("{\n\t.reg .pred p;\n\t"                                       \
        "mbarrier.try_wait.parity.acquire.cta.shared::cta.b64 p, [%1], %2;\n\t" \
        "selp.b32 %0, 1, 0, p;\n\t}" : "=r"(_d) : "r"(_m), "r"(_p) : "memory"); \
    if (!_d) {                                                                  \
        asm volatile("{\n\t.reg .pred P1;\n\t"                                  \
        "WL%=:\n\t"                                                             \
        "mbarrier.try_wait.parity.acquire.cta.shared::cta.b64 P1, [%0], %1, 0x989680;\n\t" \
        "@P1 bra.uni WD%=;\n\t"                                                 \
        "bra.uni WL%=;\n\t"                                                     \
        "WD%=:\n\t}" :: "r"(_m), "r"(_p) : "memory");                           \
    } } while (0)

__device__ __forceinline__ void tma_2d(uint32_t smem_dst, const CUtensorMap* map,
                                       int32_t cx, int32_t cy, uint32_t mbar) {
    asm volatile(
        "cp.async.bulk.tensor.2d.shared::cta.global.tile.mbarrier::complete_tx::bytes "
        "[%0], [%1, {%2, %3}], [%4];"
        :: "r"(smem_dst), "l"(map), "r"(cx), "r"(cy), "r"(mbar) : "memory");
}

__device__ __forceinline__ uint32_t f2tf32(float v) {
    uint32_t r;
    asm("cvt.rna.tf32.f32 %0, %1;" : "=r"(r) : "f"(v));
    return r;
}

__device__ __forceinline__ void mma_tf32(float* c, const uint32_t* a, const uint32_t* b) {
    asm volatile("mma.sync.aligned.m16n8k8.row.col.f32.tf32.tf32.f32 "
        "{%0,%1,%2,%3}, {%4,%5,%6,%7}, {%8,%9}, {%0,%1,%2,%3};"
        : "+f"(c[0]), "+f"(c[1]), "+f"(c[2]), "+f"(c[3])
        : "r"(a[0]), "r"(a[1]), "r"(a[2]), "r"(a[3]), "r"(b[0]), "r"(b[1]));
}

// ===================== big GEMM =====================
// out[m][n] = relu(bias[n] + sum_k A[m][k]*Bt[n][k])
// 8 compute warps (4x2 grid of 32x64 warp tiles; 2 warps per SMSP so one
// warp's MMA issue covers the other's load phase), warp 8 = TMA producer.
// Super-stages of K=64 (4 TMA boxes / 1 barrier). Double-buffered register
// fragments: k-block kb+1 loads issue before kb's MMAs.

struct FragA { uint32_t v[2][4]; };   // [mi][reg]  (32 rows: mi 0..1)
struct FragB { uint32_t v[8][2]; };   // [ni][reg]  (64 cols: ni 0..7)

__device__ __forceinline__ void load_frags(FragA& fa, FragB& fb,
                                           const char* abase, const char* bbase,
                                           uint32_t rAbase, uint32_t rBbase,
                                           const uint32_t* cx /*[2]*/) {
    #pragma unroll
    for (int mi = 0; mi < 2; mi++)
        #pragma unroll
        for (int kh = 0; kh < 2; kh++)
            #pragma unroll
            for (int h = 0; h < 2; h++) {
                float v = *(const float*)(abase + rAbase + mi * 2048 + h * 1024 + cx[kh]);
                fa.v[mi][h + 2 * kh] = f2tf32(v);
            }
    #pragma unroll
    for (int ni = 0; ni < 8; ni++)
        #pragma unroll
        for (int kh = 0; kh < 2; kh++)
            fb.v[ni][kh] = *(const uint32_t*)(bbase + rBbase + ni * 1024 + cx[kh]);
}

__device__ __forceinline__ void mma_block(float acc[2][8][4], const FragA& fa, const FragB& fb) {
    #pragma unroll
    for (int mi = 0; mi < 2; mi++)
        #pragma unroll
        for (int ni = 0; ni < 8; ni++)
            mma_tf32(acc[mi][ni], fa.v[mi], fb.v[ni]);
}

__global__ void __launch_bounds__(BIG_THREADS, 1)
gcn_big_gemm(const __grid_constant__ CUtensorMap tmA,
             const __grid_constant__ CUtensorMap tmB,
             const float* __restrict__ bias,
             float* __restrict__ out) {
    extern __shared__ __align__(1024) char smem[];
    const uint32_t base = smem_u32(smem);
    const int tid  = threadIdx.x;
    const int wid  = tid >> 5;
    const int lane = tid & 31;
    const int m0   = blockIdx.x * TILE_M;

    if (tid == 0) {
        for (int s = 0; s < SSTAGES; s++) {
            MBAR_INIT(base + SM_FULL + s * 8, 1);
            MBAR_INIT(base + SM_DONE + s * 8, 8);
        }
    }
    __syncthreads();

    if (wid == 8) {
        // -------- TMA producer --------
        if (lane == 0) {
            const CUtensorMap* pA = &tmA;
            const CUtensorMap* pB = &tmB;
            int ss = 0, ph = 1;
            for (int i = 0; i < SITERS; i++) {
                MBAR_WAIT(base + SM_DONE + ss * 8, (uint32_t)ph);
                uint32_t full = base + SM_FULL + ss * 8;
                MBAR_EXPECT_TX(full, SS_TX);
                uint32_t aslot = base + SM_A + ss * A_SS_BYTES;
                uint32_t bslot = base + SM_B + ss * B_SS_BYTES;
                int k0 = i * KSUPER;
                tma_2d(aslot,         pA, k0,      m0, full);
                tma_2d(aslot + 16384, pA, k0 + 32, m0, full);
                tma_2d(bslot,         pB, k0,      0,  full);
                tma_2d(bslot + 16384, pB, k0 + 32, 0,  full);
                if (++ss == SSTAGES) { ss = 0; ph ^= 1; }
            }
        }
    } else {
        // -------- compute warps --------
        const int g  = lane >> 2;
        const int tg = lane & 3;
        const int wm = wid >> 1;      // 0..3  (m: 32-row band)
        const int wn = wid & 1;       // 0..1  (n: 64-col band)
        const uint32_t xorv = (uint32_t)g << 4;

        const uint32_t rAbase = (uint32_t)(wm * 32 + g) * 128;  // + mi*2048 + h*1024
        const uint32_t rBbase = (uint32_t)(wn * 64 + g) * 128;  // + ni*1024

        // colx[ksub][kh]: byte col within a 32-float half, SW128-xored
        uint32_t colx[4][2];
        #pragma unroll
        for (int ks = 0; ks < 4; ks++)
            #pragma unroll
            for (int kh = 0; kh < 2; kh++)
                colx[ks][kh] = ((uint32_t)(ks * 32 + kh * 16 + tg * 4)) ^ xorv;

        float acc[2][8][4];
        #pragma unroll
        for (int mi = 0; mi < 2; mi++)
            #pragma unroll
            for (int ni = 0; ni < 8; ni++)
                #pragma unroll
                for (int q = 0; q < 4; q++) acc[mi][ni][q] = 0.0f;

        FragA afA, afB2;
        FragB bfA, bfB2;

        int ss = 0, ph = 0;
        const char* aslot = smem + SM_A;
        const char* bslot = smem + SM_B;

        MBAR_WAIT(base + SM_FULL, 0u);
        load_frags(afA, bfA, aslot, bslot, rAbase, rBbase, colx[0]);

        for (int i = 0; i < SITERS; i++) {
            // kb = 0..7 ; khalf = kb>>2 ; ksub = kb&3 ; buffers alternate
            #pragma unroll
            for (int kb = 0; kb < 8; kb++) {
                const int nkb = kb + 1;
                if (kb < 7) {
                    const char* ah = aslot + ((nkb >> 2) ? 16384 : 0);
                    const char* bh = bslot + ((nkb >> 2) ? 16384 : 0);
                    if ((kb & 1) == 0) {
                        load_frags(afB2, bfB2, ah, bh, rAbase, rBbase, colx[nkb & 3]);
                        mma_block(acc, afA, bfA);
                    } else {
                        load_frags(afA, bfA, ah, bh, rAbase, rBbase, colx[nkb & 3]);
                        mma_block(acc, afB2, bfB2);
                    }
                } else {
                    // kb == 7 : cur buffer is afB2/bfB2 (7 is odd)
                    mma_block(acc, afB2, bfB2);   // forces LDS drain before arrive
                    if (lane == 0) MBAR_ARRIVE(base + SM_DONE + ss * 8);
                    // advance slot
                    int ssn = ss + 1, phn = ph;
                    if (ssn == SSTAGES) { ssn = 0; phn ^= 1; }
                    if (i < SITERS - 1) {
                        MBAR_WAIT(base + SM_FULL + ssn * 8, (uint32_t)phn);
                        const char* an = smem + SM_A + ssn * A_SS_BYTES;
                        const char* bn = smem + SM_B + ssn * B_SS_BYTES;
                        load_frags(afA, bfA, an, bn, rAbase, rBbase, colx[0]);
                        aslot = an; bslot = bn;
                    }
                    ss = ssn; ph = phn;
                }
            }
        }

        // -------- epilogue: bias + relu, write fp32 --------
        #pragma unroll
        for (int ni = 0; ni < 8; ni++) {
            const int c0 = wn * 64 + ni * 8 + tg * 2;
            const float bb0 = __ldg(&bias[c0]);
            const float bb1 = __ldg(&bias[c0 + 1]);
            #pragma unroll
            for (int mi = 0; mi < 2; mi++) {
                const int r0 = m0 + wm * 32 + mi * 16 + g;
                float2 v0, v1;
                v0.x = fmaxf(acc[mi][ni][0] + bb0, 0.0f);
                v0.y = fmaxf(acc[mi][ni][1] + bb1, 0.0f);
                v1.x = fmaxf(acc[mi][ni][2] + bb0, 0.0f);
                v1.y = fmaxf(acc[mi][ni][3] + bb1, 0.0f);
                *reinterpret_cast<float2*>(out + (size_t)r0 * HDIM + c0) = v0;
                *reinterpret_cast<float2*>(out + (size_t)(r0 + 8) * HDIM + c0) = v1;
            }
        }
    }
}

// ===================== small GEMM: outT[n][node] = sum_f in[node][f] * w[f][n] =====================
__global__ void __launch_bounds__(256)
gcn_in_gemm(const float* __restrict__ in, const float* __restrict__ w, float* __restrict__ outT) {
    extern __shared__ float sm[];
    float* ws = sm;                       // [128][128]
    float* xs = sm + HDIM * HDIM;         // [128][129] padded
    const int tid = threadIdx.x;
    const int n0 = blockIdx.x * 128;

    for (int i = tid; i < (HDIM * HDIM) / 4; i += 256)
        reinterpret_cast<float4*>(ws)[i] = reinterpret_cast<const float4*>(w)[i];
    {
        const int col = tid & 127;
        const int r0  = tid >> 7;
        for (int r = r0; r < 128; r += 2)
            xs[r * XS_PAD + col] = in[(size_t)(n0 + r) * HDIM + col];
    }
    __syncthreads();

    const int cg   = tid >> 5;
    const int lane = tid & 31;

    float acc[4][16];
    #pragma unroll
    for (int k = 0; k < 4; k++)
        #pragma unroll
        for (int j = 0; j < 16; j++) acc[k][j] = 0.0f;

    #pragma unroll 4
    for (int f = 0; f < HDIM; f++) {
        float a[4];
        #pragma unroll
        for (int k = 0; k < 4; k++)
            a[k] = xs[(lane + 32 * k) * XS_PAD + f];
        const float4* wr = reinterpret_cast<const float4*>(ws + f * HDIM + cg * 16);
        float4 w0 = wr[0], w1 = wr[1], w2 = wr[2], w3 = wr[3];
        #pragma unroll
        for (int k = 0; k < 4; k++) {
            acc[k][0]  += a[k] * w0.x;  acc[k][1]  += a[k] * w0.y;
            acc[k][2]  += a[k] * w0.z;  acc[k][3]  += a[k] * w0.w;
            acc[k][4]  += a[k] * w1.x;  acc[k][5]  += a[k] * w1.y;
            acc[k][6]  += a[k] * w1.z;  acc[k][7]  += a[k] * w1.w;
            acc[k][8]  += a[k] * w2.x;  acc[k][9]  += a[k] * w2.y;
            acc[k][10] += a[k] * w2.z;  acc[k][11] += a[k] * w2.w;
            acc[k][12] += a[k] * w3.x;  acc[k][13] += a[k] * w3.y;
            acc[k][14] += a[k] * w3.z;  acc[k][15] += a[k] * w3.w;
        }
    }
    #pragma unroll
    for (int j = 0; j < 16; j++) {
        const int col = cg * 16 + j;
        #pragma unroll
        for (int k = 0; k < 4; k++) {
            uint32_t t = f2tf32(acc[k][j]);
            *reinterpret_cast<uint32_t*>(&outT[(size_t)col * NNODES + n0 + lane + 32 * k]) = t;
        }
    }
}

// ===================== head: out[i][c] = b3[c] + sum_n h[i][n] * w3[n][c] =====================
__global__ void __launch_bounds__(256)
gcn_head(const float* __restrict__ h, const float* __restrict__ w3,
         const float* __restrict__ b3, float* __restrict__ out) {
    const int i = blockIdx.x * 256 + threadIdx.x;
    if (i >= NNODES) return;
    float s0 = __ldg(&b3[0]), s1 = __ldg(&b3[1]);
    const float4* hv = reinterpret_cast<const float4*>(h + (size_t)i * HDIM);
    #pragma unroll
    for (int q = 0; q < 32; q++) {
        float4 v = __ldg(&hv[q]);
        const int n = q * 4;
        s0 += v.x * __ldg(&w3[(n + 0) * 2 + 0]); s1 += v.x * __ldg(&w3[(n + 0) * 2 + 1]);
        s0 += v.y * __ldg(&w3[(n + 1) * 2 + 0]); s1 += v.y * __ldg(&w3[(n + 1) * 2 + 1]);
        s0 += v.z * __ldg(&w3[(n + 2) * 2 + 0]); s1 += v.z * __ldg(&w3[(n + 2) * 2 + 1]);
        s0 += v.w * __ldg(&w3[(n + 3) * 2 + 0]); s1 += v.w * __ldg(&w3[(n + 3) * 2 + 1]);
    }
    out[i * 2 + 0] = s0;
    out[i * 2 + 1] = s1;
}

// ===================== host =====================
typedef CUresult (*PFN_encodeTiled)(CUtensorMap*, CUtensorMapDataType, cuuint32_t, void*,
                                    const cuuint64_t*, const cuuint64_t*, const cuuint32_t*,
                                    const cuuint32_t*, CUtensorMapInterleave, CUtensorMapSwizzle,
                                    CUtensorMapL2promotion, CUtensorMapFloatOOBfill);

extern "C" void kernel_launch(void* const* d_in, const int* in_sizes, int n_in,
                              void* d_out, int out_size) {
    const float* x   = (const float*)d_in[0];
    const float* adj = (const float*)d_in[1];
    const float* w1  = (const float*)d_in[2];
    const float* b1  = (const float*)d_in[3];
    const float* w2  = (const float*)d_in[4];
    const float* b2  = (const float*)d_in[5];
    const float* w3  = (const float*)d_in[6];
    const float* b3  = (const float*)d_in[7];
    float* out = (float*)d_out;

    void* bufA = nullptr;
    void* bufH = nullptr;
    cudaGetSymbolAddress(&bufA, g_bufA);
    cudaGetSymbolAddress(&bufH, g_bufH);

    void* fn = nullptr;
    cudaDriverEntryPointQueryResult qres;
    cudaGetDriverEntryPointByVersion("cuTensorMapEncodeTiled", &fn, 12000,
                                     cudaEnableDefault, &qres);
    PFN_encodeTiled encode = (PFN_encodeTiled)fn;

    CUtensorMap tmA{}, tmB{};
    {
        cuuint64_t dims[2]   = {NNODES, NNODES};
        cuuint64_t stride[1] = {NNODES * sizeof(float)};
        cuuint32_t box[2]    = {32, TILE_M};
        cuuint32_t es[2]     = {1, 1};
        encode(&tmA, CU_TENSOR_MAP_DATA_TYPE_FLOAT32, 2, (void*)adj, dims, stride, box, es,
               CU_TENSOR_MAP_INTERLEAVE_NONE, CU_TENSOR_MAP_SWIZZLE_128B,
               CU_TENSOR_MAP_L2_PROMOTION_L2_128B, CU_TENSOR_MAP_FLOAT_OOB_FILL_NONE);
    }
    {
        cuuint64_t dims[2]   = {NNODES, HDIM};
        cuuint64_t stride[1] = {NNODES * sizeof(float)};
        cuuint32_t box[2]    = {32, TILE_N};
        cuuint32_t es[2]     = {1, 1};
        encode(&tmB, CU_TENSOR_MAP_DATA_TYPE_FLOAT32, 2, bufA, dims, stride, box, es,
               CU_TENSOR_MAP_INTERLEAVE_NONE, CU_TENSOR_MAP_SWIZZLE_128B,
               CU_TENSOR_MAP_L2_PROMOTION_L2_128B, CU_TENSOR_MAP_FLOAT_OOB_FILL_NONE);
    }

    cudaFuncSetAttribute(gcn_big_gemm, cudaFuncAttributeMaxDynamicSharedMemorySize, SMEM_TOTAL);
    cudaFuncSetAttribute(gcn_in_gemm, cudaFuncAttributeMaxDynamicSharedMemorySize, IN_SMEM);

    gcn_in_gemm<<<NNODES / 128, 256, IN_SMEM>>>(x, w1, (float*)bufA);
    gcn_big_gemm<<<NNODES / TILE_M, BIG_THREADS, SMEM_TOTAL>>>(tmA, tmB, b1, (float*)bufH);
    gcn_in_gemm<<<NNODES / 128, 256, IN_SMEM>>>((const float*)bufH, w2, (float*)bufA);
    gcn_big_gemm<<<NNODES / TILE_M, BIG_THREADS, SMEM_TOTAL>>>(tmA, tmB, b2, (float*)bufH);
    gcn_head<<<NNODES / 256, 256>>>((const float*)bufH, w3, b3, out);
}